// round 2
// baseline (speedup 1.0000x reference)
#include <cuda_runtime.h>
#include <math.h>
#include <float.h>

#define NN 50000
#define EE 800000

// ---------------- device scratch (no allocs allowed) ----------------
__device__ int   g_deg[NN];
__device__ int   g_off[NN + 1];
__device__ int   g_cur[NN];
__device__ int   g_srcs[EE];
__device__ float g_logdeg[NN];
__device__ float g_delta_sum;
__device__ float g_amp[NN];
__device__ float g_att[NN];
__device__ float g_aggs[(size_t)NN * 1024];   // max 4*256 per node
__device__ float g_hA[(size_t)NN * 256];
__device__ float g_hB[(size_t)NN * 256];
__device__ float g_colsum[256];
__device__ float g_colssq[256];
__device__ float g_bnscale[256];
__device__ float g_bnshift[256];

// ---------------- graph preprocessing ----------------
__global__ void k_zero_graph() {
    int i = blockIdx.x * blockDim.x + threadIdx.x;
    if (i < NN) { g_deg[i] = 0; g_cur[i] = 0; }
    if (i == 0) g_delta_sum = 0.f;
}

__global__ void k_degree(const int* __restrict__ dst) {
    int i = blockIdx.x * blockDim.x + threadIdx.x;
    if (i < EE) atomicAdd(&g_deg[dst[i]], 1);
}

// single-block scan of degrees -> CSR offsets; also log1p(deg) and sum for delta
__global__ void k_scan() {
    __shared__ int   sh[1024];
    __shared__ float shf[1024];
    __shared__ int   s_run;
    int tid = threadIdx.x;
    if (tid == 0) s_run = 0;
    float lsum = 0.f;
    __syncthreads();
    for (int base = 0; base < NN; base += 1024) {
        int i = base + tid;
        int v = (i < NN) ? g_deg[i] : 0;
        sh[tid] = v;
        __syncthreads();
        for (int off = 1; off < 1024; off <<= 1) {
            int t = (tid >= off) ? sh[tid - off] : 0;
            __syncthreads();
            sh[tid] += t;
            __syncthreads();
        }
        if (i < NN) {
            g_off[i] = s_run + sh[tid] - v;   // exclusive scan
            float ld = log1pf((float)v);
            g_logdeg[i] = ld;
            lsum += ld;
        }
        __syncthreads();
        if (tid == 0) s_run += sh[1023];
        __syncthreads();
    }
    if (tid == 0) g_off[NN] = s_run;
    shf[tid] = lsum;
    __syncthreads();
    for (int s = 512; s > 0; s >>= 1) {
        if (tid < s) shf[tid] += shf[tid + s];
        __syncthreads();
    }
    if (tid == 0) g_delta_sum = shf[0];
}

__global__ void k_fill(const int* __restrict__ src, const int* __restrict__ dst) {
    int i = blockIdx.x * blockDim.x + threadIdx.x;
    if (i < EE) {
        int dd = dst[i];
        int pos = atomicAdd(&g_cur[dd], 1);
        g_srcs[g_off[dd] + pos] = src[i];
    }
}

__global__ void k_ampatt() {
    int i = blockIdx.x * blockDim.x + threadIdx.x;
    if (i >= NN) return;
    float delta = g_delta_sum / (float)NN;
    float ld = g_logdeg[i];
    g_amp[i] = ld / delta;
    g_att[i] = (ld > 0.f) ? (delta / fmaxf(ld, 1e-6f)) : 1.f;
}

// ---------------- per-layer aggregation (CSR, atomic-free) ----------------
// one thread per (node, feature); d is a power of two, shift = log2(d)
__global__ void k_agg(const float* __restrict__ xin, int d, int shift) {
    int t = blockIdx.x * blockDim.x + threadIdx.x;
    int node = t >> shift;
    if (node >= NN) return;
    int f = t & (d - 1);
    int beg = g_off[node], end = g_off[node + 1];
    float s = 0.f, ssq = 0.f, mn = FLT_MAX, mx = -FLT_MAX;
    for (int e = beg; e < end; e++) {
        int src = g_srcs[e];
        float v = xin[(src << shift) + f];
        s += v; ssq += v * v;
        mn = fminf(mn, v); mx = fmaxf(mx, v);
    }
    int deg = end - beg;
    float cnt = (float)(deg > 0 ? deg : 1);
    float mean = s / cnt;
    float msq = ssq / cnt;
    float sd = sqrtf(fmaxf(msq - mean * mean, 0.f) + 1e-5f);
    if (deg == 0) { mn = 0.f; mx = 0.f; }
    float* a = g_aggs + ((size_t)node << (shift + 2));
    a[f] = mean; a[d + f] = mn; a[2 * d + f] = mx; a[3 * d + f] = sd;
}

// ---------------- fused GEMM (implicit feat) + bias + ReLU + BN stats ----------------
__device__ __forceinline__ float feat_val(const float* __restrict__ xin,
                                          int row, int k, int d) {
    if (k < d) return xin[row * d + k];
    int k2 = k - d;
    int fourd = d << 2;
    float scale = 1.0f;
    if (k2 >= 2 * fourd)      { k2 -= 2 * fourd; scale = g_att[row]; }
    else if (k2 >= fourd)     { k2 -= fourd;     scale = g_amp[row]; }
    return g_aggs[(size_t)row * fourd + k2] * scale;
}

#define AP 68   // A smem pitch: multiple of 4 (aligned float4), odd/32-residue to limit conflicts

__global__ void k_gemm(const float* __restrict__ xin, const float* __restrict__ Wm,
                       const float* __restrict__ bias, float* __restrict__ hout,
                       int d, int dout) {
    __shared__ __align__(16) float As[32 * AP];
    __shared__ __align__(16) float Bs[32 * 64];
    __shared__ float s_cs[64];
    __shared__ float s_cq[64];
    int tid = threadIdx.x;
    int tx = tid & 15, ty = tid >> 4;
    int m0 = blockIdx.x * 64;
    int n0 = blockIdx.y * 64;
    int K = 13 * d;
    float acc[4][4];
#pragma unroll
    for (int i = 0; i < 4; i++)
#pragma unroll
        for (int j = 0; j < 4; j++) acc[i][j] = 0.f;

    for (int k0 = 0; k0 < K; k0 += 32) {
        // A tile: 64 rows x 32 k ; threads read k-contiguous (coalesced), store [k][m]
#pragma unroll
        for (int i = 0; i < 8; i++) {
            int idx = i * 256 + tid;
            int m  = idx >> 5;
            int kk = idx & 31;
            int row = m0 + m;
            float v = 0.f;
            if (row < NN) v = feat_val(xin, row, k0 + kk, d);
            As[kk * AP + m] = v;
        }
        // B tile: 32 k x 64 n ; n-contiguous (coalesced), store [k][n]
#pragma unroll
        for (int i = 0; i < 8; i++) {
            int idx = i * 256 + tid;
            int kk = idx >> 6;
            int n  = idx & 63;
            Bs[kk * 64 + n] = Wm[(k0 + kk) * dout + (n0 + n)];
        }
        __syncthreads();
#pragma unroll
        for (int kk = 0; kk < 32; kk++) {
            float4 a4 = *reinterpret_cast<const float4*>(&As[kk * AP + ty * 4]);
            float4 b4 = *reinterpret_cast<const float4*>(&Bs[kk * 64 + tx * 4]);
            float a[4] = {a4.x, a4.y, a4.z, a4.w};
            float b[4] = {b4.x, b4.y, b4.z, b4.w};
#pragma unroll
            for (int i = 0; i < 4; i++)
#pragma unroll
                for (int j = 0; j < 4; j++)
                    acc[i][j] = fmaf(a[i], b[j], acc[i][j]);
        }
        __syncthreads();
    }

    // epilogue: bias + relu + write + column sum/sumsq for BN
    if (tid < 64) { s_cs[tid] = 0.f; s_cq[tid] = 0.f; }
    __syncthreads();
    float csum[4], cssq[4];
#pragma unroll
    for (int j = 0; j < 4; j++) { csum[j] = 0.f; cssq[j] = 0.f; }
#pragma unroll
    for (int i = 0; i < 4; i++) {
        int row = m0 + ty * 4 + i;
        if (row >= NN) continue;
#pragma unroll
        for (int j = 0; j < 4; j++) {
            int c = n0 + tx * 4 + j;
            float v = acc[i][j] + bias[c];
            v = fmaxf(v, 0.f);
            hout[row * dout + c] = v;
            csum[j] += v; cssq[j] += v * v;
        }
    }
#pragma unroll
    for (int j = 0; j < 4; j++) {
        atomicAdd(&s_cs[tx * 4 + j], csum[j]);
        atomicAdd(&s_cq[tx * 4 + j], cssq[j]);
    }
    __syncthreads();
    if (tid < 64) {
        atomicAdd(&g_colsum[n0 + tid], s_cs[tid]);
        atomicAdd(&g_colssq[n0 + tid], s_cq[tid]);
    }
}

// ---------------- batchnorm ----------------
__global__ void k_zero_bn() {
    int i = threadIdx.x;
    g_colsum[i] = 0.f; g_colssq[i] = 0.f;
}

__global__ void k_bnfinal(const float* __restrict__ gamma,
                          const float* __restrict__ beta, int dout) {
    int c = threadIdx.x;
    if (c >= dout) return;
    float mean = g_colsum[c] / (float)NN;
    float var  = g_colssq[c] / (float)NN - mean * mean;
    float inv  = rsqrtf(var + 1e-5f);
    g_bnscale[c] = gamma[c] * inv;
    g_bnshift[c] = beta[c] - mean * inv * gamma[c];
}

__global__ void k_bnapply(float* __restrict__ h, int mask, int total) {
    int i = blockIdx.x * blockDim.x + threadIdx.x;
    if (i >= total) return;
    int c = i & mask;
    h[i] = h[i] * g_bnscale[c] + g_bnshift[c];
}

// ---------------- classifier: [N,64] @ [64,10] + bc ----------------
__global__ void k_cls(const float* __restrict__ h, const float* __restrict__ Wc,
                      const float* __restrict__ bc, float* __restrict__ out) {
    __shared__ float sW[640];
    __shared__ float sb[16];
    int tid = threadIdx.x;
    for (int i = tid; i < 640; i += 256) sW[i] = Wc[i];
    if (tid < 10) sb[tid] = bc[tid];
    __syncthreads();
    int gwarp = (blockIdx.x * 256 + tid) >> 5;
    int lane = tid & 31;
    if (gwarp >= NN) return;
    float v1 = h[gwarp * 64 + lane];
    float v2 = h[gwarp * 64 + 32 + lane];
    float acc[10];
#pragma unroll
    for (int c = 0; c < 10; c++)
        acc[c] = v1 * sW[lane * 10 + c] + v2 * sW[(lane + 32) * 10 + c];
#pragma unroll
    for (int off = 16; off > 0; off >>= 1)
#pragma unroll
        for (int c = 0; c < 10; c++)
            acc[c] += __shfl_down_sync(0xffffffffu, acc[c], off);
    if (lane == 0)
#pragma unroll
        for (int c = 0; c < 10; c++)
            out[gwarp * 10 + c] = acc[c] + sb[c];
}

// ---------------- launch ----------------
extern "C" void kernel_launch(void* const* d_in, const int* in_sizes, int n_in,
                              void* d_out, int out_size) {
    const float* x  = (const float*)d_in[0];
    const int*   ei = (const int*)d_in[1];
    const int* src = ei;
    const int* dst = ei + EE;

    float *hA, *hB;
    cudaGetSymbolAddress((void**)&hA, g_hA);
    cudaGetSymbolAddress((void**)&hB, g_hB);

    k_zero_graph<<<(NN + 255) / 256, 256>>>();
    k_degree<<<(EE + 255) / 256, 256>>>(dst);
    k_scan<<<1, 1024>>>();
    k_fill<<<(EE + 255) / 256, 256>>>(src, dst);
    k_ampatt<<<(NN + 255) / 256, 256>>>();

    int dims[5]   = {64, 128, 256, 128, 64};
    int shifts[4] = {6, 7, 8, 7};
    const float* xin = x;
    float* bufs[2] = {hA, hB};

    for (int l = 0; l < 4; l++) {
        int d = dims[l], dout = dims[l + 1];
        const float* W  = (const float*)d_in[2 + 4 * l];
        const float* b  = (const float*)d_in[3 + 4 * l];
        const float* gm = (const float*)d_in[4 + 4 * l];
        const float* bt = (const float*)d_in[5 + 4 * l];
        float* hout = bufs[l & 1];

        k_agg<<<((NN << shifts[l]) + 255) / 256, 256>>>(xin, d, shifts[l]);
        k_zero_bn<<<1, 256>>>();
        dim3 grid((NN + 63) / 64, dout / 64);
        k_gemm<<<grid, 256>>>(xin, W, b, hout, d, dout);
        k_bnfinal<<<1, 256>>>(gm, bt, dout);
        k_bnapply<<<(NN * dout + 255) / 256, 256>>>(hout, dout - 1, NN * dout);
        xin = hout;
    }

    k_cls<<<NN / 8, 256>>>(xin, (const float*)d_in[18], (const float*)d_in[19],
                           (float*)d_out);
}

// round 10
// speedup vs baseline: 2.1117x; 2.1117x over previous
#include <cuda_runtime.h>
#include <cuda_bf16.h>
#include <math.h>
#include <float.h>
#include <stdint.h>

#define NN 50000
#define EE 800000

// ---------------- device scratch (no allocs allowed) ----------------
__device__ int   g_deg[NN];
__device__ int   g_off[NN + 1];
__device__ int   g_cur[NN];
__device__ int   g_srcs[EE];
__device__ float g_logdeg[NN];
__device__ float g_delta_sum;
__device__ float g_amp[NN];
__device__ float g_att[NN];
__device__ float g_aggs[(size_t)NN * 1024];   // max 4*256 per node
__device__ float g_hA[(size_t)NN * 256];
__device__ float g_hB[(size_t)NN * 256];
__device__ uint32_t g_WtHi[212992];           // packed bf16x2, max dout*K/2 words
__device__ uint32_t g_WtLo[212992];
__device__ float g_colsum[256];
__device__ float g_colssq[256];
__device__ float g_bnscale[256];
__device__ float g_bnshift[256];

// split v into bf16 hi + bf16 lo (residual); pack 2 consecutive k into one word
__device__ __forceinline__ void split2(float v0, float v1, uint32_t& hi, uint32_t& lo) {
    __nv_bfloat16 h0 = __float2bfloat16(v0);
    __nv_bfloat16 h1 = __float2bfloat16(v1);
    float r0 = v0 - __bfloat162float(h0);
    float r1 = v1 - __bfloat162float(h1);
    __nv_bfloat16 l0 = __float2bfloat16(r0);
    __nv_bfloat16 l1 = __float2bfloat16(r1);
    hi = (uint32_t)__bfloat16_as_ushort(h0) | ((uint32_t)__bfloat16_as_ushort(h1) << 16);
    lo = (uint32_t)__bfloat16_as_ushort(l0) | ((uint32_t)__bfloat16_as_ushort(l1) << 16);
}

// ---------------- graph preprocessing ----------------
__global__ void k_zero_graph() {
    int i = blockIdx.x * blockDim.x + threadIdx.x;
    if (i < NN) { g_deg[i] = 0; g_cur[i] = 0; }
    if (i == 0) g_delta_sum = 0.f;
}

__global__ void k_degree(const int* __restrict__ dst) {
    int i = blockIdx.x * blockDim.x + threadIdx.x;
    if (i < EE) atomicAdd(&g_deg[dst[i]], 1);
}

__global__ void k_scan() {
    __shared__ int   sh[1024];
    __shared__ float shf[1024];
    __shared__ int   s_run;
    int tid = threadIdx.x;
    if (tid == 0) s_run = 0;
    float lsum = 0.f;
    __syncthreads();
    for (int base = 0; base < NN; base += 1024) {
        int i = base + tid;
        int v = (i < NN) ? g_deg[i] : 0;
        sh[tid] = v;
        __syncthreads();
        for (int off = 1; off < 1024; off <<= 1) {
            int t = (tid >= off) ? sh[tid - off] : 0;
            __syncthreads();
            sh[tid] += t;
            __syncthreads();
        }
        if (i < NN) {
            g_off[i] = s_run + sh[tid] - v;
            float ld = log1pf((float)v);
            g_logdeg[i] = ld;
            lsum += ld;
        }
        __syncthreads();
        if (tid == 0) s_run += sh[1023];
        __syncthreads();
    }
    if (tid == 0) g_off[NN] = s_run;
    shf[tid] = lsum;
    __syncthreads();
    for (int s = 512; s > 0; s >>= 1) {
        if (tid < s) shf[tid] += shf[tid + s];
        __syncthreads();
    }
    if (tid == 0) g_delta_sum = shf[0];
}

__global__ void k_fill(const int* __restrict__ src, const int* __restrict__ dst) {
    int i = blockIdx.x * blockDim.x + threadIdx.x;
    if (i < EE) {
        int dd = dst[i];
        int pos = atomicAdd(&g_cur[dd], 1);
        g_srcs[g_off[dd] + pos] = src[i];
    }
}

__global__ void k_ampatt() {
    int i = blockIdx.x * blockDim.x + threadIdx.x;
    if (i >= NN) return;
    float delta = g_delta_sum / (float)NN;
    float ld = g_logdeg[i];
    g_amp[i] = ld / delta;
    g_att[i] = (ld > 0.f) ? (delta / fmaxf(ld, 1e-6f)) : 1.f;
}

// ---------------- aggregation (CSR, atomic-free) ----------------
__global__ void k_agg(const float* __restrict__ xin, int d, int shift) {
    int t = blockIdx.x * blockDim.x + threadIdx.x;
    int node = t >> shift;
    if (node >= NN) return;
    int f = t & (d - 1);
    int beg = g_off[node], end = g_off[node + 1];
    float s = 0.f, ssq = 0.f, mn = FLT_MAX, mx = -FLT_MAX;
    for (int e = beg; e < end; e++) {
        int src = g_srcs[e];
        float v = xin[(src << shift) + f];
        s += v; ssq += v * v;
        mn = fminf(mn, v); mx = fmaxf(mx, v);
    }
    int deg = end - beg;
    float cnt = (float)(deg > 0 ? deg : 1);
    float mean = s / cnt;
    float msq = ssq / cnt;
    float sd = sqrtf(fmaxf(msq - mean * mean, 0.f) + 1e-5f);
    if (deg == 0) { mn = 0.f; mx = 0.f; }
    float* a = g_aggs + ((size_t)node << (shift + 2));
    a[f] = mean; a[d + f] = mn; a[2 * d + f] = mx; a[3 * d + f] = sd;
}

// ---- W transpose + bf16 split: WtHi/Lo[n][k/2] packed pairs, k-major rows ----
__global__ void k_transpose(const float* __restrict__ W, uint32_t* __restrict__ WtHi,
                            uint32_t* __restrict__ WtLo, int K, int dout) {
    __shared__ float t[32][33];
    int kb = blockIdx.x * 32, nb = blockIdx.y * 32;
    int tx = threadIdx.x, ty = threadIdx.y;
    for (int i = ty; i < 32; i += 8) t[i][tx] = W[(kb + i) * dout + nb + tx];
    __syncthreads();
    int tid = ty * 32 + tx;
#pragma unroll
    for (int it = 0; it < 2; it++) {
        int w = it * 256 + tid;           // 512 words per tile
        int n = w >> 4, kw = w & 15;
        float v0 = t[2 * kw][n], v1 = t[2 * kw + 1][n];
        uint32_t hw, lw;
        split2(v0, v1, hw, lw);
        size_t o = (size_t)(nb + n) * (K >> 1) + (kb >> 1) + kw;
        WtHi[o] = hw;
        WtLo[o] = lw;
    }
}

// ---------------- split-bf16 mma.sync GEMM (implicit feat A) + fused epilogue ----------------
// CTA tile 128(M) x 64(N), 256 threads = 4x2 warps of 32x32.
// Warp tile: 2(M) x 4(N) m16n8k16 tiles; K-tile = 32 (2 chunks of 16).
// Per chunk per tile: c += Ahi*Bhi + Ahi*Blo + Alo*Bhi  (3 HMMA).
#define MMA_BF16(cc, aa, bb) \
    asm volatile("mma.sync.aligned.m16n8k16.row.col.f32.bf16.bf16.f32 " \
                 "{%0,%1,%2,%3}, {%4,%5,%6,%7}, {%8,%9}, {%0,%1,%2,%3};" \
                 : "+f"((cc)[0]), "+f"((cc)[1]), "+f"((cc)[2]), "+f"((cc)[3]) \
                 : "r"((aa)[0]), "r"((aa)[1]), "r"((aa)[2]), "r"((aa)[3]), \
                   "r"((bb)[0]), "r"((bb)[1]))

__global__ void __launch_bounds__(256, 2)
k_gemm_mma(const float* __restrict__ xin, const uint32_t* __restrict__ WtHi,
           const uint32_t* __restrict__ WtLo, const float* __restrict__ bias,
           float* __restrict__ hout, int d, int dout) {
    __shared__ uint32_t As_hi[128][20];   // 16 kwords/row, stride 20 -> conflict-free
    __shared__ uint32_t As_lo[128][20];
    __shared__ uint32_t Bs_hi[64][20];
    __shared__ uint32_t Bs_lo[64][20];
    __shared__ float s_cs[64];
    __shared__ float s_cq[64];
    __shared__ float sbias[64];

    int tid = threadIdx.x;
    int wid = tid >> 5;
    int lane = tid & 31;
    int wm = (wid & 3) * 32;
    int wn = (wid >> 2) * 32;
    int q = lane >> 2;      // 0..7
    int r = lane & 3;       // 0..3
    int m0 = blockIdx.x * 128;
    int n0 = blockIdx.y * 64;
    int K = 13 * d;
    int Kw = K >> 1;

    if (tid < 64) sbias[tid] = bias[n0 + tid];

    float c[2][4][4];
#pragma unroll
    for (int i = 0; i < 2; i++)
#pragma unroll
        for (int j = 0; j < 4; j++)
#pragma unroll
            for (int v = 0; v < 4; v++) c[i][j][v] = 0.f;

    for (int k0 = 0; k0 < K; k0 += 32) {
        // select feat source for this k-tile (tiles never straddle segment bounds)
        const float* srcb;
        int stride, mode;
        if (k0 < d) { srcb = xin + k0; stride = d; mode = 0; }
        else {
            int k2 = k0 - d, fourd = d << 2;
            mode = 1 + k2 / fourd;
            srcb = g_aggs + (k2 - (mode - 1) * fourd);
            stride = fourd;
        }
        __syncthreads();
        // A tile: 128 rows x 32 k, split into bf16 hi/lo packed pairs
#pragma unroll
        for (int it = 0; it < 4; it++) {
            int idx = it * 256 + tid;
            int row = idx >> 3, c4 = idx & 7;
            int grow = m0 + row;
            uint32_t h0 = 0, h1 = 0, l0 = 0, l1 = 0;
            if (grow < NN) {
                float4 v = *(const float4*)(srcb + (size_t)grow * stride + c4 * 4);
                float sc = 1.f;
                if (mode == 2) sc = g_amp[grow];
                else if (mode == 3) sc = g_att[grow];
                split2(v.x * sc, v.y * sc, h0, l0);
                split2(v.z * sc, v.w * sc, h1, l1);
            }
            uint2 hh = {h0, h1}, ll = {l0, l1};
            *(uint2*)&As_hi[row][c4 * 2] = hh;
            *(uint2*)&As_lo[row][c4 * 2] = ll;
        }
        // B tile: 64 n-rows x 16 kwords from pre-split Wt (1 uint4 per thread per array)
        {
            int n = tid >> 2, w4 = tid & 3;
            size_t o = (size_t)(n0 + n) * Kw + (k0 >> 1) + w4 * 4;
            uint4 vh = *(const uint4*)(WtHi + o);
            uint4 vl = *(const uint4*)(WtLo + o);
            *(uint4*)&Bs_hi[n][w4 * 4] = vh;
            *(uint4*)&Bs_lo[n][w4 * 4] = vl;
        }
        __syncthreads();
#pragma unroll
        for (int ch = 0; ch < 2; ch++) {
            int kb2 = ch * 8;
            uint32_t ah[2][4], al[2][4], bh[4][2], bl[4][2];
#pragma unroll
            for (int i = 0; i < 2; i++) {
                int ra = wm + i * 16 + q;
                ah[i][0] = As_hi[ra][kb2 + r];     ah[i][1] = As_hi[ra + 8][kb2 + r];
                ah[i][2] = As_hi[ra][kb2 + r + 4]; ah[i][3] = As_hi[ra + 8][kb2 + r + 4];
                al[i][0] = As_lo[ra][kb2 + r];     al[i][1] = As_lo[ra + 8][kb2 + r];
                al[i][2] = As_lo[ra][kb2 + r + 4]; al[i][3] = As_lo[ra + 8][kb2 + r + 4];
            }
#pragma unroll
            for (int j = 0; j < 4; j++) {
                int rb = wn + j * 8 + q;
                bh[j][0] = Bs_hi[rb][kb2 + r]; bh[j][1] = Bs_hi[rb][kb2 + r + 4];
                bl[j][0] = Bs_lo[rb][kb2 + r]; bl[j][1] = Bs_lo[rb][kb2 + r + 4];
            }
#pragma unroll
            for (int i = 0; i < 2; i++)
#pragma unroll
                for (int j = 0; j < 4; j++) {
                    MMA_BF16(c[i][j], ah[i], bh[j]);
                    MMA_BF16(c[i][j], ah[i], bl[j]);
                    MMA_BF16(c[i][j], al[i], bh[j]);
                }
        }
    }

    // ---- epilogue: bias + relu + store + BN stats ----
    __syncthreads();
    if (tid < 64) { s_cs[tid] = 0.f; s_cq[tid] = 0.f; }
    __syncthreads();
#pragma unroll
    for (int i = 0; i < 2; i++) {
#pragma unroll
        for (int half = 0; half < 2; half++) {
            int row = m0 + wm + i * 16 + q + half * 8;
            bool valid = row < NN;
#pragma unroll
            for (int j = 0; j < 4; j++) {
#pragma unroll
                for (int e = 0; e < 2; e++) {
                    int lc = wn + j * 8 + 2 * r + e;
                    float v = c[i][j][half * 2 + e] + sbias[lc];
                    v = fmaxf(v, 0.f);
                    if (valid) {
                        hout[(size_t)row * dout + n0 + lc] = v;
                        atomicAdd(&s_cs[lc], v);
                        atomicAdd(&s_cq[lc], v * v);
                    }
                }
            }
        }
    }
    __syncthreads();
    if (tid < 64) {
        atomicAdd(&g_colsum[n0 + tid], s_cs[tid]);
        atomicAdd(&g_colssq[n0 + tid], s_cq[tid]);
    }
}

// ---------------- batchnorm ----------------
__global__ void k_zero_bn() {
    int i = threadIdx.x;
    g_colsum[i] = 0.f; g_colssq[i] = 0.f;
}

__global__ void k_bnfinal(const float* __restrict__ gamma,
                          const float* __restrict__ beta, int dout) {
    int c = threadIdx.x;
    if (c >= dout) return;
    float mean = g_colsum[c] / (float)NN;
    float var  = g_colssq[c] / (float)NN - mean * mean;
    float inv  = rsqrtf(var + 1e-5f);
    g_bnscale[c] = gamma[c] * inv;
    g_bnshift[c] = beta[c] - mean * inv * gamma[c];
}

__global__ void k_bnapply(float* __restrict__ h, int mask, int total) {
    int i = blockIdx.x * blockDim.x + threadIdx.x;
    if (i >= total) return;
    int c = i & mask;
    h[i] = h[i] * g_bnscale[c] + g_bnshift[c];
}

// ---------------- classifier ----------------
__global__ void k_cls(const float* __restrict__ h, const float* __restrict__ Wc,
                      const float* __restrict__ bc, float* __restrict__ out) {
    __shared__ float sW[640];
    __shared__ float sb[16];
    int tid = threadIdx.x;
    for (int i = tid; i < 640; i += 256) sW[i] = Wc[i];
    if (tid < 10) sb[tid] = bc[tid];
    __syncthreads();
    int gwarp = (blockIdx.x * 256 + tid) >> 5;
    int lane = tid & 31;
    if (gwarp >= NN) return;
    float v1 = h[gwarp * 64 + lane];
    float v2 = h[gwarp * 64 + 32 + lane];
    float acc[10];
#pragma unroll
    for (int c = 0; c < 10; c++)
        acc[c] = v1 * sW[lane * 10 + c] + v2 * sW[(lane + 32) * 10 + c];
#pragma unroll
    for (int off = 16; off > 0; off >>= 1)
#pragma unroll
        for (int c = 0; c < 10; c++)
            acc[c] += __shfl_down_sync(0xffffffffu, acc[c], off);
    if (lane == 0)
#pragma unroll
        for (int c = 0; c < 10; c++)
            out[gwarp * 10 + c] = acc[c] + sb[c];
}

// ---------------- launch ----------------
extern "C" void kernel_launch(void* const* d_in, const int* in_sizes, int n_in,
                              void* d_out, int out_size) {
    const float* x  = (const float*)d_in[0];
    const int*   ei = (const int*)d_in[1];
    const int* src = ei;
    const int* dst = ei + EE;

    float *hA, *hB;
    uint32_t *WtHi, *WtLo;
    cudaGetSymbolAddress((void**)&hA, g_hA);
    cudaGetSymbolAddress((void**)&hB, g_hB);
    cudaGetSymbolAddress((void**)&WtHi, g_WtHi);
    cudaGetSymbolAddress((void**)&WtLo, g_WtLo);

    k_zero_graph<<<(NN + 255) / 256, 256>>>();
    k_degree<<<(EE + 255) / 256, 256>>>(dst);
    k_scan<<<1, 1024>>>();
    k_fill<<<(EE + 255) / 256, 256>>>(src, dst);
    k_ampatt<<<(NN + 255) / 256, 256>>>();

    int dims[5]   = {64, 128, 256, 128, 64};
    int shifts[4] = {6, 7, 8, 7};
    const float* xin = x;
    float* bufs[2] = {hA, hB};

    for (int l = 0; l < 4; l++) {
        int d = dims[l], dout = dims[l + 1];
        int K = 13 * d;
        const float* W  = (const float*)d_in[2 + 4 * l];
        const float* b  = (const float*)d_in[3 + 4 * l];
        const float* gm = (const float*)d_in[4 + 4 * l];
        const float* bt = (const float*)d_in[5 + 4 * l];
        float* hout = bufs[l & 1];

        k_agg<<<((NN << shifts[l]) + 255) / 256, 256>>>(xin, d, shifts[l]);
        dim3 tg(K / 32, dout / 32);
        k_transpose<<<tg, dim3(32, 8)>>>(W, WtHi, WtLo, K, dout);
        k_zero_bn<<<1, 256>>>();

        dim3 grid((NN + 127) / 128, dout / 64);
        k_gemm_mma<<<grid, 256>>>(xin, WtHi, WtLo, b, hout, d, dout);

        k_bnfinal<<<1, 256>>>(gm, bt, dout);
        k_bnapply<<<(NN * dout + 255) / 256, 256>>>(hout, dout - 1, NN * dout);
        xin = hout;
    }

    k_cls<<<NN / 8, 256>>>(xin, (const float*)d_in[18], (const float*)d_in[19],
                           (float*)d_out);
}

// round 11
// speedup vs baseline: 2.8479x; 1.3486x over previous
#include <cuda_runtime.h>
#include <cuda_bf16.h>
#include <math.h>
#include <float.h>
#include <stdint.h>

#define NN 50000
#define EE 800000

// ---------------- device scratch (no allocs allowed) ----------------
__device__ int   g_deg[NN];
__device__ int   g_off[NN + 1];
__device__ int   g_cur[NN];
__device__ int   g_srcs[EE];
__device__ float g_logdeg[NN];
__device__ float g_delta_sum;
__device__ float g_amp[NN];
__device__ float g_att[NN];
__device__ float g_hA[(size_t)NN * 256];
__device__ float g_hB[(size_t)NN * 256];
__device__ uint32_t g_featHi[(size_t)NN * 1664];  // packed bf16x2 hi, 13*256/2 words max
__device__ uint32_t g_featLo[(size_t)NN * 1664];
__device__ uint32_t g_WtHi[212992];               // packed bf16x2, max dout*K/2 words
__device__ uint32_t g_WtLo[212992];
__device__ float g_colsum[256];
__device__ float g_colssq[256];
__device__ float g_bnscale[256];
__device__ float g_bnshift[256];

// split v into bf16 hi + bf16 lo (residual); pack 2 consecutive k into one word
__device__ __forceinline__ void split2(float v0, float v1, uint32_t& hi, uint32_t& lo) {
    __nv_bfloat16 h0 = __float2bfloat16(v0);
    __nv_bfloat16 h1 = __float2bfloat16(v1);
    float r0 = v0 - __bfloat162float(h0);
    float r1 = v1 - __bfloat162float(h1);
    __nv_bfloat16 l0 = __float2bfloat16(r0);
    __nv_bfloat16 l1 = __float2bfloat16(r1);
    hi = (uint32_t)__bfloat16_as_ushort(h0) | ((uint32_t)__bfloat16_as_ushort(h1) << 16);
    lo = (uint32_t)__bfloat16_as_ushort(l0) | ((uint32_t)__bfloat16_as_ushort(l1) << 16);
}

// ---------------- graph preprocessing ----------------
__global__ void k_zero_graph() {
    int i = blockIdx.x * blockDim.x + threadIdx.x;
    if (i < NN) { g_deg[i] = 0; g_cur[i] = 0; }
    if (i == 0) g_delta_sum = 0.f;
}

__global__ void k_degree(const int* __restrict__ dst) {
    int i = blockIdx.x * blockDim.x + threadIdx.x;
    if (i < EE) atomicAdd(&g_deg[dst[i]], 1);
}

__global__ void k_scan() {
    __shared__ int   sh[1024];
    __shared__ float shf[1024];
    __shared__ int   s_run;
    int tid = threadIdx.x;
    if (tid == 0) s_run = 0;
    float lsum = 0.f;
    __syncthreads();
    for (int base = 0; base < NN; base += 1024) {
        int i = base + tid;
        int v = (i < NN) ? g_deg[i] : 0;
        sh[tid] = v;
        __syncthreads();
        for (int off = 1; off < 1024; off <<= 1) {
            int t = (tid >= off) ? sh[tid - off] : 0;
            __syncthreads();
            sh[tid] += t;
            __syncthreads();
        }
        if (i < NN) {
            g_off[i] = s_run + sh[tid] - v;
            float ld = log1pf((float)v);
            g_logdeg[i] = ld;
            lsum += ld;
        }
        __syncthreads();
        if (tid == 0) s_run += sh[1023];
        __syncthreads();
    }
    if (tid == 0) g_off[NN] = s_run;
    shf[tid] = lsum;
    __syncthreads();
    for (int s = 512; s > 0; s >>= 1) {
        if (tid < s) shf[tid] += shf[tid + s];
        __syncthreads();
    }
    if (tid == 0) g_delta_sum = shf[0];
}

__global__ void k_fill(const int* __restrict__ src, const int* __restrict__ dst) {
    int i = blockIdx.x * blockDim.x + threadIdx.x;
    if (i < EE) {
        int dd = dst[i];
        int pos = atomicAdd(&g_cur[dd], 1);
        g_srcs[g_off[dd] + pos] = src[i];
    }
}

__global__ void k_ampatt() {
    int i = blockIdx.x * blockDim.x + threadIdx.x;
    if (i >= NN) return;
    float delta = g_delta_sum / (float)NN;
    float ld = g_logdeg[i];
    g_amp[i] = ld / delta;
    g_att[i] = (ld > 0.f) ? (delta / fmaxf(ld, 1e-6f)) : 1.f;
}

// ---- fused: BN-affine of prev layer + CSR aggregation + feat build + bf16 split ----
// thread per (node, feature-pair). Writes all 13 packed words for that pair.
__global__ void k_feat(const float* __restrict__ h, int d, int shiftP, int useAffine,
                       uint32_t* __restrict__ fH, uint32_t* __restrict__ fL) {
    int t = blockIdx.x * blockDim.x + threadIdx.x;
    int node = t >> shiftP;
    if (node >= NN) return;
    int pr = t & ((d >> 1) - 1);
    int f0 = pr << 1;
    float a0 = 1.f, b0 = 0.f, a1 = 1.f, b1 = 0.f;
    if (useAffine) {
        a0 = g_bnscale[f0]; b0 = g_bnshift[f0];
        a1 = g_bnscale[f0 + 1]; b1 = g_bnshift[f0 + 1];
    }
    int beg = g_off[node], end = g_off[node + 1];
    float s0 = 0.f, s1 = 0.f, q0 = 0.f, q1 = 0.f;
    float mn0 = FLT_MAX, mn1 = FLT_MAX, mx0 = -FLT_MAX, mx1 = -FLT_MAX;
    for (int e = beg; e < end; e++) {
        int src = g_srcs[e];
        float2 v = *(const float2*)(h + (size_t)src * d + f0);
        s0 += v.x; q0 += v.x * v.x; mn0 = fminf(mn0, v.x); mx0 = fmaxf(mx0, v.x);
        s1 += v.y; q1 += v.y * v.y; mn1 = fminf(mn1, v.y); mx1 = fmaxf(mx1, v.y);
    }
    int deg = end - beg;
    float cnt = (float)(deg > 0 ? deg : 1);
    float has = (deg > 0) ? 1.f : 0.f;
    float m0 = s0 / cnt, m1 = s1 / cnt, mq0 = q0 / cnt, mq1 = q1 / cnt;
    // exact affine transforms of raw moments
    float mean0 = a0 * m0 + has * b0;
    float mean1 = a1 * m1 + has * b1;
    float msq0 = a0 * a0 * mq0 + 2.f * a0 * b0 * m0 + b0 * b0 * has;
    float msq1 = a1 * a1 * mq1 + 2.f * a1 * b1 * m1 + b1 * b1 * has;
    float sd0 = sqrtf(fmaxf(msq0 - mean0 * mean0, 0.f) + 1e-5f);
    float sd1 = sqrtf(fmaxf(msq1 - mean1 * mean1, 0.f) + 1e-5f);
    float Amn0, Amx0, Amn1, Amx1;
    if (deg > 0) {
        Amn0 = (a0 >= 0.f) ? a0 * mn0 + b0 : a0 * mx0 + b0;
        Amx0 = (a0 >= 0.f) ? a0 * mx0 + b0 : a0 * mn0 + b0;
        Amn1 = (a1 >= 0.f) ? a1 * mn1 + b1 : a1 * mx1 + b1;
        Amx1 = (a1 >= 0.f) ? a1 * mx1 + b1 : a1 * mn1 + b1;
    } else {
        Amn0 = Amx0 = Amn1 = Amx1 = 0.f;
    }
    float2 xv = *(const float2*)(h + (size_t)node * d + f0);
    float X0 = a0 * xv.x + b0;
    float X1 = a1 * xv.y + b1;
    float amp = g_amp[node], att = g_att[node];

    int hd = d >> 1;
    size_t rowb = (size_t)node * (13 * hd);
    uint32_t hw, lw;
#define PUTW(wi, v0, v1) { split2((v0), (v1), hw, lw); fH[rowb + (wi)] = hw; fL[rowb + (wi)] = lw; }
    PUTW(pr, X0, X1);
    PUTW(hd + pr, mean0, mean1);
    PUTW(2 * hd + pr, Amn0, Amn1);
    PUTW(3 * hd + pr, Amx0, Amx1);
    PUTW(4 * hd + pr, sd0, sd1);
    PUTW(5 * hd + pr, mean0 * amp, mean1 * amp);
    PUTW(6 * hd + pr, Amn0 * amp, Amn1 * amp);
    PUTW(7 * hd + pr, Amx0 * amp, Amx1 * amp);
    PUTW(8 * hd + pr, sd0 * amp, sd1 * amp);
    PUTW(9 * hd + pr, mean0 * att, mean1 * att);
    PUTW(10 * hd + pr, Amn0 * att, Amn1 * att);
    PUTW(11 * hd + pr, Amx0 * att, Amx1 * att);
    PUTW(12 * hd + pr, sd0 * att, sd1 * att);
#undef PUTW
}

// ---- W transpose + bf16 split: WtHi/Lo[n][k/2] packed pairs, k-major rows ----
__global__ void k_transpose(const float* __restrict__ W, uint32_t* __restrict__ WtHi,
                            uint32_t* __restrict__ WtLo, int K, int dout) {
    __shared__ float t[32][33];
    int kb = blockIdx.x * 32, nb = blockIdx.y * 32;
    int tx = threadIdx.x, ty = threadIdx.y;
    for (int i = ty; i < 32; i += 8) t[i][tx] = W[(kb + i) * dout + nb + tx];
    __syncthreads();
    int tid = ty * 32 + tx;
#pragma unroll
    for (int it = 0; it < 2; it++) {
        int w = it * 256 + tid;
        int n = w >> 4, kw = w & 15;
        float v0 = t[2 * kw][n], v1 = t[2 * kw + 1][n];
        uint32_t hw, lw;
        split2(v0, v1, hw, lw);
        size_t o = (size_t)(nb + n) * (K >> 1) + (kb >> 1) + kw;
        WtHi[o] = hw;
        WtLo[o] = lw;
    }
}

// ---------------- split-bf16 mma.sync GEMM (pre-split feat A) + fused epilogue ----------------
#define MMA_BF16(cc, aa, bb) \
    asm volatile("mma.sync.aligned.m16n8k16.row.col.f32.bf16.bf16.f32 " \
                 "{%0,%1,%2,%3}, {%4,%5,%6,%7}, {%8,%9}, {%0,%1,%2,%3};" \
                 : "+f"((cc)[0]), "+f"((cc)[1]), "+f"((cc)[2]), "+f"((cc)[3]) \
                 : "r"((aa)[0]), "r"((aa)[1]), "r"((aa)[2]), "r"((aa)[3]), \
                   "r"((bb)[0]), "r"((bb)[1]))

__global__ void __launch_bounds__(256, 2)
k_gemm_mma(const uint32_t* __restrict__ fH, const uint32_t* __restrict__ fL,
           const uint32_t* __restrict__ WtHi, const uint32_t* __restrict__ WtLo,
           const float* __restrict__ bias, float* __restrict__ hout,
           int d, int dout) {
    __shared__ uint32_t As_hi[128][20];   // 16 kwords/row, stride 20 -> conflict-free
    __shared__ uint32_t As_lo[128][20];
    __shared__ uint32_t Bs_hi[64][20];
    __shared__ uint32_t Bs_lo[64][20];
    __shared__ float s_cs[64];
    __shared__ float s_cq[64];
    __shared__ float sbias[64];

    int tid = threadIdx.x;
    int wid = tid >> 5;
    int lane = tid & 31;
    int wm = (wid & 3) * 32;
    int wn = (wid >> 2) * 32;
    int q = lane >> 2;
    int r = lane & 3;
    int m0 = blockIdx.x * 128;
    int n0 = blockIdx.y * 64;
    int K = 13 * d;
    int Kw = K >> 1;

    if (tid < 64) sbias[tid] = bias[n0 + tid];

    float c[2][4][4];
#pragma unroll
    for (int i = 0; i < 2; i++)
#pragma unroll
        for (int j = 0; j < 4; j++)
#pragma unroll
            for (int v = 0; v < 4; v++) c[i][j][v] = 0.f;

    for (int k0 = 0; k0 < K; k0 += 32) {
        int kw0 = k0 >> 1;
        __syncthreads();
        // A tile: 128 rows x 16 kwords from pre-split feat (2 uint4 per thread per array)
#pragma unroll
        for (int it = 0; it < 2; it++) {
            int idx = it * 256 + tid;
            int row = idx >> 2, w4 = idx & 3;
            int grow = m0 + row;
            uint4 vh = {0u, 0u, 0u, 0u}, vl = {0u, 0u, 0u, 0u};
            if (grow < NN) {
                size_t o = (size_t)grow * Kw + kw0 + w4 * 4;
                vh = *(const uint4*)(fH + o);
                vl = *(const uint4*)(fL + o);
            }
            *(uint4*)&As_hi[row][w4 * 4] = vh;
            *(uint4*)&As_lo[row][w4 * 4] = vl;
        }
        // B tile: 64 n-rows x 16 kwords
        {
            int n = tid >> 2, w4 = tid & 3;
            size_t o = (size_t)(n0 + n) * Kw + kw0 + w4 * 4;
            uint4 vh = *(const uint4*)(WtHi + o);
            uint4 vl = *(const uint4*)(WtLo + o);
            *(uint4*)&Bs_hi[n][w4 * 4] = vh;
            *(uint4*)&Bs_lo[n][w4 * 4] = vl;
        }
        __syncthreads();
#pragma unroll
        for (int ch = 0; ch < 2; ch++) {
            int kb2 = ch * 8;
            uint32_t ah[2][4], al[2][4], bh[4][2], bl[4][2];
#pragma unroll
            for (int i = 0; i < 2; i++) {
                int ra = wm + i * 16 + q;
                ah[i][0] = As_hi[ra][kb2 + r];     ah[i][1] = As_hi[ra + 8][kb2 + r];
                ah[i][2] = As_hi[ra][kb2 + r + 4]; ah[i][3] = As_hi[ra + 8][kb2 + r + 4];
                al[i][0] = As_lo[ra][kb2 + r];     al[i][1] = As_lo[ra + 8][kb2 + r];
                al[i][2] = As_lo[ra][kb2 + r + 4]; al[i][3] = As_lo[ra + 8][kb2 + r + 4];
            }
#pragma unroll
            for (int j = 0; j < 4; j++) {
                int rb = wn + j * 8 + q;
                bh[j][0] = Bs_hi[rb][kb2 + r]; bh[j][1] = Bs_hi[rb][kb2 + r + 4];
                bl[j][0] = Bs_lo[rb][kb2 + r]; bl[j][1] = Bs_lo[rb][kb2 + r + 4];
            }
#pragma unroll
            for (int i = 0; i < 2; i++)
#pragma unroll
                for (int j = 0; j < 4; j++) {
                    MMA_BF16(c[i][j], ah[i], bh[j]);
                    MMA_BF16(c[i][j], ah[i], bl[j]);
                    MMA_BF16(c[i][j], al[i], bh[j]);
                }
        }
    }

    // ---- epilogue: bias + relu + store (raw, pre-BN) + BN stats ----
    __syncthreads();
    if (tid < 64) { s_cs[tid] = 0.f; s_cq[tid] = 0.f; }
    __syncthreads();
#pragma unroll
    for (int i = 0; i < 2; i++) {
#pragma unroll
        for (int half = 0; half < 2; half++) {
            int row = m0 + wm + i * 16 + q + half * 8;
            bool valid = row < NN;
#pragma unroll
            for (int j = 0; j < 4; j++) {
#pragma unroll
                for (int e = 0; e < 2; e++) {
                    int lc = wn + j * 8 + 2 * r + e;
                    float v = c[i][j][half * 2 + e] + sbias[lc];
                    v = fmaxf(v, 0.f);
                    if (valid) {
                        hout[(size_t)row * dout + n0 + lc] = v;
                        atomicAdd(&s_cs[lc], v);
                        atomicAdd(&s_cq[lc], v * v);
                    }
                }
            }
        }
    }
    __syncthreads();
    if (tid < 64) {
        atomicAdd(&g_colsum[n0 + tid], s_cs[tid]);
        atomicAdd(&g_colssq[n0 + tid], s_cq[tid]);
    }
}

// ---------------- batchnorm stats -> affine coefficients ----------------
__global__ void k_zero_bn() {
    int i = threadIdx.x;
    g_colsum[i] = 0.f; g_colssq[i] = 0.f;
}

__global__ void k_bnfinal(const float* __restrict__ gamma,
                          const float* __restrict__ beta, int dout) {
    int c = threadIdx.x;
    if (c >= dout) return;
    float mean = g_colsum[c] / (float)NN;
    float var  = g_colssq[c] / (float)NN - mean * mean;
    float inv  = rsqrtf(var + 1e-5f);
    g_bnscale[c] = gamma[c] * inv;
    g_bnshift[c] = beta[c] - mean * inv * gamma[c];
}

// ---------------- classifier (applies final BN affine inline) ----------------
__global__ void k_cls(const float* __restrict__ h, const float* __restrict__ Wc,
                      const float* __restrict__ bc, float* __restrict__ out) {
    __shared__ float sW[640];
    __shared__ float sb[16];
    int tid = threadIdx.x;
    for (int i = tid; i < 640; i += 256) sW[i] = Wc[i];
    if (tid < 10) sb[tid] = bc[tid];
    __syncthreads();
    int gwarp = (blockIdx.x * 256 + tid) >> 5;
    int lane = tid & 31;
    if (gwarp >= NN) return;
    float v1 = h[gwarp * 64 + lane] * g_bnscale[lane] + g_bnshift[lane];
    float v2 = h[gwarp * 64 + 32 + lane] * g_bnscale[lane + 32] + g_bnshift[lane + 32];
    float acc[10];
#pragma unroll
    for (int c = 0; c < 10; c++)
        acc[c] = v1 * sW[lane * 10 + c] + v2 * sW[(lane + 32) * 10 + c];
#pragma unroll
    for (int off = 16; off > 0; off >>= 1)
#pragma unroll
        for (int c = 0; c < 10; c++)
            acc[c] += __shfl_down_sync(0xffffffffu, acc[c], off);
    if (lane == 0)
#pragma unroll
        for (int c = 0; c < 10; c++)
            out[gwarp * 10 + c] = acc[c] + sb[c];
}

// ---------------- launch ----------------
extern "C" void kernel_launch(void* const* d_in, const int* in_sizes, int n_in,
                              void* d_out, int out_size) {
    const float* x  = (const float*)d_in[0];
    const int*   ei = (const int*)d_in[1];
    const int* src = ei;
    const int* dst = ei + EE;

    float *hA, *hB;
    uint32_t *WtHi, *WtLo, *fH, *fL;
    cudaGetSymbolAddress((void**)&hA, g_hA);
    cudaGetSymbolAddress((void**)&hB, g_hB);
    cudaGetSymbolAddress((void**)&WtHi, g_WtHi);
    cudaGetSymbolAddress((void**)&WtLo, g_WtLo);
    cudaGetSymbolAddress((void**)&fH, g_featHi);
    cudaGetSymbolAddress((void**)&fL, g_featLo);

    k_zero_graph<<<(NN + 255) / 256, 256>>>();
    k_degree<<<(EE + 255) / 256, 256>>>(dst);
    k_scan<<<1, 1024>>>();
    k_fill<<<(EE + 255) / 256, 256>>>(src, dst);
    k_ampatt<<<(NN + 255) / 256, 256>>>();

    int dims[5]   = {64, 128, 256, 128, 64};
    int shiftsP[4] = {5, 6, 7, 6};   // log2(d/2)
    const float* xin = x;
    float* bufs[2] = {hA, hB};

    for (int l = 0; l < 4; l++) {
        int d = dims[l], dout = dims[l + 1];
        int K = 13 * d;
        const float* W  = (const float*)d_in[2 + 4 * l];
        const float* b  = (const float*)d_in[3 + 4 * l];
        const float* gm = (const float*)d_in[4 + 4 * l];
        const float* bt = (const float*)d_in[5 + 4 * l];
        float* hout = bufs[l & 1];

        k_feat<<<((NN << shiftsP[l]) + 255) / 256, 256>>>(xin, d, shiftsP[l], l > 0, fH, fL);
        dim3 tg(K / 32, dout / 32);
        k_transpose<<<tg, dim3(32, 8)>>>(W, WtHi, WtLo, K, dout);
        k_zero_bn<<<1, 256>>>();

        dim3 grid((NN + 127) / 128, dout / 64);
        k_gemm_mma<<<grid, 256>>>(fH, fL, WtHi, WtLo, b, hout, d, dout);

        k_bnfinal<<<1, 256>>>(gm, bt, dout);
        xin = hout;
    }

    k_cls<<<NN / 8, 256>>>(xin, (const float*)d_in[18], (const float*)d_in[19],
                           (float*)d_out);
}

// round 12
// speedup vs baseline: 3.4148x; 1.1990x over previous
#include <cuda_runtime.h>
#include <cuda_bf16.h>
#include <math.h>
#include <float.h>
#include <stdint.h>

#define NN 50000
#define EE 800000

// ---------------- device scratch (no allocs allowed) ----------------
__device__ int   g_deg[NN];
__device__ int   g_off[NN + 1];
__device__ int   g_cur[NN];
__device__ int   g_srcs[EE];
__device__ float g_logdeg[NN];
__device__ float g_delta_sum;
__device__ float g_amp[NN];
__device__ float g_att[NN];
__device__ float g_hA[(size_t)NN * 256];
__device__ float g_hB[(size_t)NN * 256];
__device__ uint32_t g_featHi[(size_t)NN * 1664];  // packed bf16x2 hi, 13*256/2 words max
__device__ uint32_t g_featLo[(size_t)NN * 1664];
__device__ uint32_t g_WtHi[212992];               // packed bf16x2, max dout*K/2 words
__device__ uint32_t g_WtLo[212992];
__device__ float g_colsum[256];
__device__ float g_colssq[256];
__device__ float g_bnscale[256];
__device__ float g_bnshift[256];

// split v into bf16 hi + bf16 lo (residual); pack 2 consecutive k into one word
__device__ __forceinline__ void split2(float v0, float v1, uint32_t& hi, uint32_t& lo) {
    __nv_bfloat16 h0 = __float2bfloat16(v0);
    __nv_bfloat16 h1 = __float2bfloat16(v1);
    float r0 = v0 - __bfloat162float(h0);
    float r1 = v1 - __bfloat162float(h1);
    __nv_bfloat16 l0 = __float2bfloat16(r0);
    __nv_bfloat16 l1 = __float2bfloat16(r1);
    hi = (uint32_t)__bfloat16_as_ushort(h0) | ((uint32_t)__bfloat16_as_ushort(h1) << 16);
    lo = (uint32_t)__bfloat16_as_ushort(l0) | ((uint32_t)__bfloat16_as_ushort(l1) << 16);
}

__device__ __forceinline__ uint32_t smem_u32(const void* p) {
    uint32_t a;
    asm("{ .reg .u64 t; cvta.to.shared.u64 t, %1; cvt.u32.u64 %0, t; }" : "=r"(a) : "l"(p));
    return a;
}
__device__ __forceinline__ void cp16(uint32_t saddr, const void* g, bool pred) {
    int sz = pred ? 16 : 0;
    asm volatile("cp.async.cg.shared.global [%0], [%1], 16, %2;"
                 :: "r"(saddr), "l"(g), "r"(sz) : "memory");
}
#define CP_COMMIT() asm volatile("cp.async.commit_group;" ::: "memory")
#define CP_WAIT1()  asm volatile("cp.async.wait_group 1;" ::: "memory")
#define CP_WAIT0()  asm volatile("cp.async.wait_group 0;" ::: "memory")

// ---------------- graph preprocessing ----------------
__global__ void k_zero_graph() {
    int i = blockIdx.x * blockDim.x + threadIdx.x;
    if (i < NN) { g_deg[i] = 0; g_cur[i] = 0; }
    if (i == 0) g_delta_sum = 0.f;
}

__global__ void k_degree(const int* __restrict__ dst) {
    int i = blockIdx.x * blockDim.x + threadIdx.x;
    if (i < EE) atomicAdd(&g_deg[dst[i]], 1);
}

__global__ void k_scan() {
    __shared__ int   sh[1024];
    __shared__ float shf[1024];
    __shared__ int   s_run;
    int tid = threadIdx.x;
    if (tid == 0) s_run = 0;
    float lsum = 0.f;
    __syncthreads();
    for (int base = 0; base < NN; base += 1024) {
        int i = base + tid;
        int v = (i < NN) ? g_deg[i] : 0;
        sh[tid] = v;
        __syncthreads();
        for (int off = 1; off < 1024; off <<= 1) {
            int t = (tid >= off) ? sh[tid - off] : 0;
            __syncthreads();
            sh[tid] += t;
            __syncthreads();
        }
        if (i < NN) {
            g_off[i] = s_run + sh[tid] - v;
            float ld = log1pf((float)v);
            g_logdeg[i] = ld;
            lsum += ld;
        }
        __syncthreads();
        if (tid == 0) s_run += sh[1023];
        __syncthreads();
    }
    if (tid == 0) g_off[NN] = s_run;
    shf[tid] = lsum;
    __syncthreads();
    for (int s = 512; s > 0; s >>= 1) {
        if (tid < s) shf[tid] += shf[tid + s];
        __syncthreads();
    }
    if (tid == 0) g_delta_sum = shf[0];
}

__global__ void k_fill(const int* __restrict__ src, const int* __restrict__ dst) {
    int i = blockIdx.x * blockDim.x + threadIdx.x;
    if (i < EE) {
        int dd = dst[i];
        int pos = atomicAdd(&g_cur[dd], 1);
        g_srcs[g_off[dd] + pos] = src[i];
    }
}

__global__ void k_ampatt() {
    int i = blockIdx.x * blockDim.x + threadIdx.x;
    if (i >= NN) return;
    float delta = g_delta_sum / (float)NN;
    float ld = g_logdeg[i];
    g_amp[i] = ld / delta;
    g_att[i] = (ld > 0.f) ? (delta / fmaxf(ld, 1e-6f)) : 1.f;
}

// ---- fused: BN-affine of prev layer + CSR aggregation + feat build + bf16 split ----
__global__ void k_feat(const float* __restrict__ h, int d, int shiftP, int useAffine,
                       uint32_t* __restrict__ fH, uint32_t* __restrict__ fL) {
    int t = blockIdx.x * blockDim.x + threadIdx.x;
    int node = t >> shiftP;
    if (node >= NN) return;
    int pr = t & ((d >> 1) - 1);
    int f0 = pr << 1;
    float a0 = 1.f, b0 = 0.f, a1 = 1.f, b1 = 0.f;
    if (useAffine) {
        a0 = g_bnscale[f0]; b0 = g_bnshift[f0];
        a1 = g_bnscale[f0 + 1]; b1 = g_bnshift[f0 + 1];
    }
    int beg = g_off[node], end = g_off[node + 1];
    float s0 = 0.f, s1 = 0.f, q0 = 0.f, q1 = 0.f;
    float mn0 = FLT_MAX, mn1 = FLT_MAX, mx0 = -FLT_MAX, mx1 = -FLT_MAX;
    for (int e = beg; e < end; e++) {
        int src = g_srcs[e];
        float2 v = *(const float2*)(h + (size_t)src * d + f0);
        s0 += v.x; q0 += v.x * v.x; mn0 = fminf(mn0, v.x); mx0 = fmaxf(mx0, v.x);
        s1 += v.y; q1 += v.y * v.y; mn1 = fminf(mn1, v.y); mx1 = fmaxf(mx1, v.y);
    }
    int deg = end - beg;
    float cnt = (float)(deg > 0 ? deg : 1);
    float has = (deg > 0) ? 1.f : 0.f;
    float m0 = s0 / cnt, m1 = s1 / cnt, mq0 = q0 / cnt, mq1 = q1 / cnt;
    float mean0 = a0 * m0 + has * b0;
    float mean1 = a1 * m1 + has * b1;
    float msq0 = a0 * a0 * mq0 + 2.f * a0 * b0 * m0 + b0 * b0 * has;
    float msq1 = a1 * a1 * mq1 + 2.f * a1 * b1 * m1 + b1 * b1 * has;
    float sd0 = sqrtf(fmaxf(msq0 - mean0 * mean0, 0.f) + 1e-5f);
    float sd1 = sqrtf(fmaxf(msq1 - mean1 * mean1, 0.f) + 1e-5f);
    float Amn0, Amx0, Amn1, Amx1;
    if (deg > 0) {
        Amn0 = (a0 >= 0.f) ? a0 * mn0 + b0 : a0 * mx0 + b0;
        Amx0 = (a0 >= 0.f) ? a0 * mx0 + b0 : a0 * mn0 + b0;
        Amn1 = (a1 >= 0.f) ? a1 * mn1 + b1 : a1 * mx1 + b1;
        Amx1 = (a1 >= 0.f) ? a1 * mx1 + b1 : a1 * mn1 + b1;
    } else {
        Amn0 = Amx0 = Amn1 = Amx1 = 0.f;
    }
    float2 xv = *(const float2*)(h + (size_t)node * d + f0);
    float X0 = a0 * xv.x + b0;
    float X1 = a1 * xv.y + b1;
    float amp = g_amp[node], att = g_att[node];

    int hd = d >> 1;
    size_t rowb = (size_t)node * (13 * hd);
    uint32_t hw, lw;
#define PUTW(wi, v0, v1) { split2((v0), (v1), hw, lw); fH[rowb + (wi)] = hw; fL[rowb + (wi)] = lw; }
    PUTW(pr, X0, X1);
    PUTW(hd + pr, mean0, mean1);
    PUTW(2 * hd + pr, Amn0, Amn1);
    PUTW(3 * hd + pr, Amx0, Amx1);
    PUTW(4 * hd + pr, sd0, sd1);
    PUTW(5 * hd + pr, mean0 * amp, mean1 * amp);
    PUTW(6 * hd + pr, Amn0 * amp, Amn1 * amp);
    PUTW(7 * hd + pr, Amx0 * amp, Amx1 * amp);
    PUTW(8 * hd + pr, sd0 * amp, sd1 * amp);
    PUTW(9 * hd + pr, mean0 * att, mean1 * att);
    PUTW(10 * hd + pr, Amn0 * att, Amn1 * att);
    PUTW(11 * hd + pr, Amx0 * att, Amx1 * att);
    PUTW(12 * hd + pr, sd0 * att, sd1 * att);
#undef PUTW
}

// ---- W transpose + bf16 split: WtHi/Lo[n][k/2] packed pairs, k-major rows ----
__global__ void k_transpose(const float* __restrict__ W, uint32_t* __restrict__ WtHi,
                            uint32_t* __restrict__ WtLo, int K, int dout) {
    __shared__ float t[32][33];
    int kb = blockIdx.x * 32, nb = blockIdx.y * 32;
    int tx = threadIdx.x, ty = threadIdx.y;
    for (int i = ty; i < 32; i += 8) t[i][tx] = W[(kb + i) * dout + nb + tx];
    __syncthreads();
    int tid = ty * 32 + tx;
#pragma unroll
    for (int it = 0; it < 2; it++) {
        int w = it * 256 + tid;
        int n = w >> 4, kw = w & 15;
        float v0 = t[2 * kw][n], v1 = t[2 * kw + 1][n];
        uint32_t hw, lw;
        split2(v0, v1, hw, lw);
        size_t o = (size_t)(nb + n) * (K >> 1) + (kb >> 1) + kw;
        WtHi[o] = hw;
        WtLo[o] = lw;
    }
}

// ---------------- split-bf16 mma.sync GEMM, 128x128 tile, cp.async 2-stage ----------------
// dsm layout (words): AsH [2][128][20] @0, AsL @5120, BsH @10240, BsL @15360. 81920 bytes.
#define MMA_BF16(cc, aa, b0v, b1v) \
    asm volatile("mma.sync.aligned.m16n8k16.row.col.f32.bf16.bf16.f32 " \
                 "{%0,%1,%2,%3}, {%4,%5,%6,%7}, {%8,%9}, {%0,%1,%2,%3};" \
                 : "+f"((cc)[0]), "+f"((cc)[1]), "+f"((cc)[2]), "+f"((cc)[3]) \
                 : "r"((aa)[0]), "r"((aa)[1]), "r"((aa)[2]), "r"((aa)[3]), \
                   "r"(b0v), "r"(b1v))

__global__ void __launch_bounds__(256)
k_gemm_mma(const uint32_t* __restrict__ fH, const uint32_t* __restrict__ fL,
           const uint32_t* __restrict__ WtHi, const uint32_t* __restrict__ WtLo,
           const float* __restrict__ bias, float* __restrict__ hout,
           int d, int dout) {
    extern __shared__ __align__(16) uint32_t dsm[];
    __shared__ float s_cs[128];
    __shared__ float s_cq[128];
    __shared__ float sbias[128];

    int tid = threadIdx.x;
    int wid = tid >> 5;
    int lane = tid & 31;
    int wm = (wid & 3) * 32;
    int wn = (wid >> 2) * 64;
    int q = lane >> 2;
    int r = lane & 3;
    int m0 = blockIdx.x * 128;
    int n0 = blockIdx.y * 128;
    int K = 13 * d;
    int Kw = K >> 1;
    int S = K >> 5;            // k-tiles of 32 (16 words)
    uint32_t sb = smem_u32(dsm);

    if (tid < 128) sbias[tid] = (n0 + tid < dout) ? bias[n0 + tid] : 0.f;

    float c[2][8][4];
#pragma unroll
    for (int i = 0; i < 2; i++)
#pragma unroll
        for (int j = 0; j < 8; j++)
#pragma unroll
            for (int v = 0; v < 4; v++) c[i][j][v] = 0.f;

    // stage issue: 8 cp.async per thread (A hi/lo + B hi/lo, 2 chunks each)
    auto issue = [&](int s) {
        int bb = s & 1;
        int kw0 = s << 4;
        uint32_t aH = sb + (uint32_t)(bb * 2560) * 4;
        uint32_t aL = sb + (uint32_t)(5120 + bb * 2560) * 4;
        uint32_t bH = sb + (uint32_t)(10240 + bb * 2560) * 4;
        uint32_t bL = sb + (uint32_t)(15360 + bb * 2560) * 4;
#pragma unroll
        for (int it = 0; it < 2; it++) {
            int idx = it * 256 + tid;
            int row = idx >> 2, w4 = idx & 3;
            uint32_t soff = (uint32_t)(row * 20 + w4 * 4) * 4;
            int grow = m0 + row;
            bool va = grow < NN;
            size_t oa = va ? ((size_t)grow * Kw + kw0 + w4 * 4) : 0;
            cp16(aH + soff, fH + oa, va);
            cp16(aL + soff, fL + oa, va);
            int n = n0 + row;
            bool vb = n < dout;
            size_t ob = vb ? ((size_t)n * Kw + kw0 + w4 * 4) : 0;
            cp16(bH + soff, WtHi + ob, vb);
            cp16(bL + soff, WtLo + ob, vb);
        }
    };

    issue(0);
    CP_COMMIT();

    for (int s = 0; s < S; s++) {
        if (s + 1 < S) { issue(s + 1); CP_COMMIT(); CP_WAIT1(); }
        else CP_WAIT0();
        __syncthreads();
        int bb = s & 1;
        const uint32_t* AH = dsm + bb * 2560;
        const uint32_t* AL = dsm + 5120 + bb * 2560;
        const uint32_t* BH = dsm + 10240 + bb * 2560;
        const uint32_t* BL = dsm + 15360 + bb * 2560;
#pragma unroll
        for (int ch = 0; ch < 2; ch++) {
            int kb2 = ch * 8;
            uint32_t ah[2][4], al[2][4];
#pragma unroll
            for (int i = 0; i < 2; i++) {
                int ra = (wm + i * 16 + q) * 20;
                ah[i][0] = AH[ra + kb2 + r];       ah[i][1] = AH[ra + 160 + kb2 + r];
                ah[i][2] = AH[ra + kb2 + r + 4];   ah[i][3] = AH[ra + 160 + kb2 + r + 4];
                al[i][0] = AL[ra + kb2 + r];       al[i][1] = AL[ra + 160 + kb2 + r];
                al[i][2] = AL[ra + kb2 + r + 4];   al[i][3] = AL[ra + 160 + kb2 + r + 4];
            }
#pragma unroll
            for (int j = 0; j < 8; j++) {
                int rb = (wn + j * 8 + q) * 20;
                uint32_t bh0 = BH[rb + kb2 + r], bh1 = BH[rb + kb2 + r + 4];
                uint32_t bl0 = BL[rb + kb2 + r], bl1 = BL[rb + kb2 + r + 4];
#pragma unroll
                for (int i = 0; i < 2; i++) {
                    MMA_BF16(c[i][j], ah[i], bh0, bh1);
                    MMA_BF16(c[i][j], ah[i], bl0, bl1);
                    MMA_BF16(c[i][j], al[i], bh0, bh1);
                }
            }
        }
        __syncthreads();
    }

    // ---- epilogue: bias + relu + store (raw, pre-BN) + BN stats ----
    if (tid < 128) { s_cs[tid] = 0.f; s_cq[tid] = 0.f; }
    __syncthreads();
#pragma unroll
    for (int i = 0; i < 2; i++) {
#pragma unroll
        for (int half = 0; half < 2; half++) {
            int row = m0 + wm + i * 16 + q + half * 8;
            bool valid = row < NN;
#pragma unroll
            for (int j = 0; j < 8; j++) {
#pragma unroll
                for (int e = 0; e < 2; e++) {
                    int lc = wn + j * 8 + 2 * r + e;
                    if (n0 + lc >= dout) continue;
                    float v = c[i][j][half * 2 + e] + sbias[lc];
                    v = fmaxf(v, 0.f);
                    if (valid) {
                        hout[(size_t)row * dout + n0 + lc] = v;
                        atomicAdd(&s_cs[lc], v);
                        atomicAdd(&s_cq[lc], v * v);
                    }
                }
            }
        }
    }
    __syncthreads();
    if (tid < 128 && n0 + tid < dout) {
        atomicAdd(&g_colsum[n0 + tid], s_cs[tid]);
        atomicAdd(&g_colssq[n0 + tid], s_cq[tid]);
    }
}

// ---------------- batchnorm stats -> affine coefficients ----------------
__global__ void k_zero_bn() {
    int i = threadIdx.x;
    g_colsum[i] = 0.f; g_colssq[i] = 0.f;
}

__global__ void k_bnfinal(const float* __restrict__ gamma,
                          const float* __restrict__ beta, int dout) {
    int c = threadIdx.x;
    if (c >= dout) return;
    float mean = g_colsum[c] / (float)NN;
    float var  = g_colssq[c] / (float)NN - mean * mean;
    float inv  = rsqrtf(var + 1e-5f);
    g_bnscale[c] = gamma[c] * inv;
    g_bnshift[c] = beta[c] - mean * inv * gamma[c];
}

// ---------------- classifier (applies final BN affine inline) ----------------
__global__ void k_cls(const float* __restrict__ h, const float* __restrict__ Wc,
                      const float* __restrict__ bc, float* __restrict__ out) {
    __shared__ float sW[640];
    __shared__ float sb[16];
    int tid = threadIdx.x;
    for (int i = tid; i < 640; i += 256) sW[i] = Wc[i];
    if (tid < 10) sb[tid] = bc[tid];
    __syncthreads();
    int gwarp = (blockIdx.x * 256 + tid) >> 5;
    int lane = tid & 31;
    if (gwarp >= NN) return;
    float v1 = h[gwarp * 64 + lane] * g_bnscale[lane] + g_bnshift[lane];
    float v2 = h[gwarp * 64 + 32 + lane] * g_bnscale[lane + 32] + g_bnshift[lane + 32];
    float acc[10];
#pragma unroll
    for (int c = 0; c < 10; c++)
        acc[c] = v1 * sW[lane * 10 + c] + v2 * sW[(lane + 32) * 10 + c];
#pragma unroll
    for (int off = 16; off > 0; off >>= 1)
#pragma unroll
        for (int c = 0; c < 10; c++)
            acc[c] += __shfl_down_sync(0xffffffffu, acc[c], off);
    if (lane == 0)
#pragma unroll
        for (int c = 0; c < 10; c++)
            out[gwarp * 10 + c] = acc[c] + sb[c];
}

// ---------------- launch ----------------
extern "C" void kernel_launch(void* const* d_in, const int* in_sizes, int n_in,
                              void* d_out, int out_size) {
    const float* x  = (const float*)d_in[0];
    const int*   ei = (const int*)d_in[1];
    const int* src = ei;
    const int* dst = ei + EE;

    float *hA, *hB;
    uint32_t *WtHi, *WtLo, *fH, *fL;
    cudaGetSymbolAddress((void**)&hA, g_hA);
    cudaGetSymbolAddress((void**)&hB, g_hB);
    cudaGetSymbolAddress((void**)&WtHi, g_WtHi);
    cudaGetSymbolAddress((void**)&WtLo, g_WtLo);
    cudaGetSymbolAddress((void**)&fH, g_featHi);
    cudaGetSymbolAddress((void**)&fL, g_featLo);

    cudaFuncSetAttribute(k_gemm_mma, cudaFuncAttributeMaxDynamicSharedMemorySize, 81920);

    k_zero_graph<<<(NN + 255) / 256, 256>>>();
    k_degree<<<(EE + 255) / 256, 256>>>(dst);
    k_scan<<<1, 1024>>>();
    k_fill<<<(EE + 255) / 256, 256>>>(src, dst);
    k_ampatt<<<(NN + 255) / 256, 256>>>();

    int dims[5]   = {64, 128, 256, 128, 64};
    int shiftsP[4] = {5, 6, 7, 6};   // log2(d/2)
    const float* xin = x;
    float* bufs[2] = {hA, hB};

    for (int l = 0; l < 4; l++) {
        int d = dims[l], dout = dims[l + 1];
        int K = 13 * d;
        const float* W  = (const float*)d_in[2 + 4 * l];
        const float* b  = (const float*)d_in[3 + 4 * l];
        const float* gm = (const float*)d_in[4 + 4 * l];
        const float* bt = (const float*)d_in[5 + 4 * l];
        float* hout = bufs[l & 1];

        k_feat<<<((NN << shiftsP[l]) + 255) / 256, 256>>>(xin, d, shiftsP[l], l > 0, fH, fL);
        dim3 tg(K / 32, dout / 32);
        k_transpose<<<tg, dim3(32, 8)>>>(W, WtHi, WtLo, K, dout);
        k_zero_bn<<<1, 256>>>();

        dim3 grid((NN + 127) / 128, (dout + 127) / 128);
        k_gemm_mma<<<grid, 256, 81920>>>(fH, fL, WtHi, WtLo, b, hout, d, dout);

        k_bnfinal<<<1, 256>>>(gm, bt, dout);
        xin = hout;
    }

    k_cls<<<NN / 8, 256>>>(xin, (const float*)d_in[18], (const float*)d_in[19],
                           (float*)d_out);
}

// round 13
// speedup vs baseline: 3.9690x; 1.1623x over previous
#include <cuda_runtime.h>
#include <cuda_bf16.h>
#include <math.h>
#include <float.h>
#include <stdint.h>

#define NN 50000
#define EE 800000

// ---------------- device scratch (no allocs allowed) ----------------
__device__ int   g_deg[NN];
__device__ int   g_off[NN + 1];
__device__ int   g_cur[NN];
__device__ int   g_srcs[EE];
__device__ float g_logdeg[NN];
__device__ float g_delta_sum;
__device__ float g_amp[NN];
__device__ float g_att[NN];
__device__ float g_hA[(size_t)NN * 256];
__device__ float g_hB[(size_t)NN * 256];
__device__ uint32_t g_featHi[(size_t)NN * 640];   // packed bf16x2 hi, 5*256/2 words max
__device__ uint32_t g_featLo[(size_t)NN * 640];
__device__ uint32_t g_WtHi[212992];               // packed bf16x2, max dout*13d/2 words
__device__ uint32_t g_WtLo[212992];
__device__ float g_colsum[256];
__device__ float g_colssq[256];
__device__ float g_bnscale[256];
__device__ float g_bnshift[256];

// split v into bf16 hi + bf16 lo (residual); pack 2 consecutive k into one word
__device__ __forceinline__ void split2(float v0, float v1, uint32_t& hi, uint32_t& lo) {
    __nv_bfloat16 h0 = __float2bfloat16(v0);
    __nv_bfloat16 h1 = __float2bfloat16(v1);
    float r0 = v0 - __bfloat162float(h0);
    float r1 = v1 - __bfloat162float(h1);
    __nv_bfloat16 l0 = __float2bfloat16(r0);
    __nv_bfloat16 l1 = __float2bfloat16(r1);
    hi = (uint32_t)__bfloat16_as_ushort(h0) | ((uint32_t)__bfloat16_as_ushort(h1) << 16);
    lo = (uint32_t)__bfloat16_as_ushort(l0) | ((uint32_t)__bfloat16_as_ushort(l1) << 16);
}

__device__ __forceinline__ uint32_t smem_u32(const void* p) {
    uint32_t a;
    asm("{ .reg .u64 t; cvta.to.shared.u64 t, %1; cvt.u32.u64 %0, t; }" : "=r"(a) : "l"(p));
    return a;
}
__device__ __forceinline__ void cp16(uint32_t saddr, const void* g, bool pred) {
    int sz = pred ? 16 : 0;
    asm volatile("cp.async.cg.shared.global [%0], [%1], 16, %2;"
                 :: "r"(saddr), "l"(g), "r"(sz) : "memory");
}
#define CP_COMMIT() asm volatile("cp.async.commit_group;" ::: "memory")
#define CP_WAIT1()  asm volatile("cp.async.wait_group 1;" ::: "memory")
#define CP_WAIT0()  asm volatile("cp.async.wait_group 0;" ::: "memory")

// ---------------- graph preprocessing ----------------
__global__ void k_zero_graph() {
    int i = blockIdx.x * blockDim.x + threadIdx.x;
    if (i < NN) { g_deg[i] = 0; g_cur[i] = 0; }
    if (i == 0) g_delta_sum = 0.f;
}

__global__ void k_degree(const int* __restrict__ dst) {
    int i = blockIdx.x * blockDim.x + threadIdx.x;
    if (i < EE) atomicAdd(&g_deg[dst[i]], 1);
}

__global__ void k_scan() {
    __shared__ int   sh[1024];
    __shared__ float shf[1024];
    __shared__ int   s_run;
    int tid = threadIdx.x;
    if (tid == 0) s_run = 0;
    float lsum = 0.f;
    __syncthreads();
    for (int base = 0; base < NN; base += 1024) {
        int i = base + tid;
        int v = (i < NN) ? g_deg[i] : 0;
        sh[tid] = v;
        __syncthreads();
        for (int off = 1; off < 1024; off <<= 1) {
            int t = (tid >= off) ? sh[tid - off] : 0;
            __syncthreads();
            sh[tid] += t;
            __syncthreads();
        }
        if (i < NN) {
            g_off[i] = s_run + sh[tid] - v;
            float ld = log1pf((float)v);
            g_logdeg[i] = ld;
            lsum += ld;
        }
        __syncthreads();
        if (tid == 0) s_run += sh[1023];
        __syncthreads();
    }
    if (tid == 0) g_off[NN] = s_run;
    shf[tid] = lsum;
    __syncthreads();
    for (int s = 512; s > 0; s >>= 1) {
        if (tid < s) shf[tid] += shf[tid + s];
        __syncthreads();
    }
    if (tid == 0) g_delta_sum = shf[0];
}

__global__ void k_fill(const int* __restrict__ src, const int* __restrict__ dst) {
    int i = blockIdx.x * blockDim.x + threadIdx.x;
    if (i < EE) {
        int dd = dst[i];
        int pos = atomicAdd(&g_cur[dd], 1);
        g_srcs[g_off[dd] + pos] = src[i];
    }
}

__global__ void k_ampatt() {
    int i = blockIdx.x * blockDim.x + threadIdx.x;
    if (i >= NN) return;
    float delta = g_delta_sum / (float)NN;
    float ld = g_logdeg[i];
    g_amp[i] = ld / delta;
    g_att[i] = (ld > 0.f) ? (delta / fmaxf(ld, 1e-6f)) : 1.f;
}

// ---- fused: BN-affine of prev layer + CSR aggregation + 5d feat + bf16 split ----
// thread per (node, feature-pair). feat5 row = [x, mean, min, max, std], stride 5*(d/2) words.
__global__ void k_feat5(const float* __restrict__ h, int d, int shiftP, int useAffine,
                        uint32_t* __restrict__ fH, uint32_t* __restrict__ fL) {
    int t = blockIdx.x * blockDim.x + threadIdx.x;
    int node = t >> shiftP;
    if (node >= NN) return;
    int pr = t & ((d >> 1) - 1);
    int f0 = pr << 1;
    float a0 = 1.f, b0 = 0.f, a1 = 1.f, b1 = 0.f;
    if (useAffine) {
        a0 = g_bnscale[f0]; b0 = g_bnshift[f0];
        a1 = g_bnscale[f0 + 1]; b1 = g_bnshift[f0 + 1];
    }
    int beg = g_off[node], end = g_off[node + 1];
    float s0 = 0.f, s1 = 0.f, q0 = 0.f, q1 = 0.f;
    float mn0 = FLT_MAX, mn1 = FLT_MAX, mx0 = -FLT_MAX, mx1 = -FLT_MAX;
    for (int e = beg; e < end; e++) {
        int src = g_srcs[e];
        float2 v = *(const float2*)(h + (size_t)src * d + f0);
        s0 += v.x; q0 += v.x * v.x; mn0 = fminf(mn0, v.x); mx0 = fmaxf(mx0, v.x);
        s1 += v.y; q1 += v.y * v.y; mn1 = fminf(mn1, v.y); mx1 = fmaxf(mx1, v.y);
    }
    int deg = end - beg;
    float cnt = (float)(deg > 0 ? deg : 1);
    float has = (deg > 0) ? 1.f : 0.f;
    float m0 = s0 / cnt, m1 = s1 / cnt, mq0 = q0 / cnt, mq1 = q1 / cnt;
    float mean0 = a0 * m0 + has * b0;
    float mean1 = a1 * m1 + has * b1;
    float msq0 = a0 * a0 * mq0 + 2.f * a0 * b0 * m0 + b0 * b0 * has;
    float msq1 = a1 * a1 * mq1 + 2.f * a1 * b1 * m1 + b1 * b1 * has;
    float sd0 = sqrtf(fmaxf(msq0 - mean0 * mean0, 0.f) + 1e-5f);
    float sd1 = sqrtf(fmaxf(msq1 - mean1 * mean1, 0.f) + 1e-5f);
    float Amn0, Amx0, Amn1, Amx1;
    if (deg > 0) {
        Amn0 = (a0 >= 0.f) ? a0 * mn0 + b0 : a0 * mx0 + b0;
        Amx0 = (a0 >= 0.f) ? a0 * mx0 + b0 : a0 * mn0 + b0;
        Amn1 = (a1 >= 0.f) ? a1 * mn1 + b1 : a1 * mx1 + b1;
        Amx1 = (a1 >= 0.f) ? a1 * mx1 + b1 : a1 * mn1 + b1;
    } else {
        Amn0 = Amx0 = Amn1 = Amx1 = 0.f;
    }
    float2 xv = *(const float2*)(h + (size_t)node * d + f0);
    float X0 = a0 * xv.x + b0;
    float X1 = a1 * xv.y + b1;

    int hd = d >> 1;
    size_t rowb = (size_t)node * (5 * hd);
    uint32_t hw, lw;
#define PUTW(wi, v0, v1) { split2((v0), (v1), hw, lw); fH[rowb + (wi)] = hw; fL[rowb + (wi)] = lw; }
    PUTW(pr, X0, X1);
    PUTW(hd + pr, mean0, mean1);
    PUTW(2 * hd + pr, Amn0, Amn1);
    PUTW(3 * hd + pr, Amx0, Amx1);
    PUTW(4 * hd + pr, sd0, sd1);
#undef PUTW
}

// ---- W transpose + bf16 split: WtHi/Lo[n][k/2] packed pairs, k-major (K=13d) ----
__global__ void k_transpose(const float* __restrict__ W, uint32_t* __restrict__ WtHi,
                            uint32_t* __restrict__ WtLo, int K, int dout) {
    __shared__ float t[32][33];
    int kb = blockIdx.x * 32, nb = blockIdx.y * 32;
    int tx = threadIdx.x, ty = threadIdx.y;
    for (int i = ty; i < 32; i += 8) t[i][tx] = W[(kb + i) * dout + nb + tx];
    __syncthreads();
    int tid = ty * 32 + tx;
#pragma unroll
    for (int it = 0; it < 2; it++) {
        int w = it * 256 + tid;
        int n = w >> 4, kw = w & 15;
        float v0 = t[2 * kw][n], v1 = t[2 * kw + 1][n];
        uint32_t hw, lw;
        split2(v0, v1, hw, lw);
        size_t o = (size_t)(nb + n) * (K >> 1) + (kb >> 1) + kw;
        WtHi[o] = hw;
        WtLo[o] = lw;
    }
}

// ------- split-bf16 mma GEMM: A = feat5 (K=5d), 3 accumulator sets, epilogue combine -------
// CTA tile 128(M) x 64(N), 256 threads = 4x2 warps of 32x32, cp.async 2-stage.
// smem words/stage: A hi 2560 | A lo 2560 | [B slab t: hi 1280, lo 1280] x3  => 12800
#define MMA_BF16(cc, aa, b0v, b1v) \
    asm volatile("mma.sync.aligned.m16n8k16.row.col.f32.bf16.bf16.f32 " \
                 "{%0,%1,%2,%3}, {%4,%5,%6,%7}, {%8,%9}, {%0,%1,%2,%3};" \
                 : "+f"((cc)[0]), "+f"((cc)[1]), "+f"((cc)[2]), "+f"((cc)[3]) \
                 : "r"((aa)[0]), "r"((aa)[1]), "r"((aa)[2]), "r"((aa)[3]), \
                   "r"(b0v), "r"(b1v))

__global__ void __launch_bounds__(256)
k_gemm_mma3(const uint32_t* __restrict__ fH, const uint32_t* __restrict__ fL,
            const uint32_t* __restrict__ WtHi, const uint32_t* __restrict__ WtLo,
            const float* __restrict__ bias, float* __restrict__ hout,
            int d, int dout) {
    extern __shared__ __align__(16) uint32_t dsm[];
    __shared__ float s_cs[64];
    __shared__ float s_cq[64];
    __shared__ float sbias[64];
    __shared__ float samp[128];
    __shared__ float satt[128];

    int tid = threadIdx.x;
    int wid = tid >> 5;
    int lane = tid & 31;
    int wm = (wid & 3) * 32;
    int wn = (wid >> 2) * 32;
    int q = lane >> 2;
    int r = lane & 3;
    int m0 = blockIdx.x * 128;
    int n0 = blockIdx.y * 64;
    int KwA = (5 * d) >> 1;      // feat5 row stride in words
    int Kw13 = (13 * d) >> 1;    // Wt row stride in words
    int S = (5 * d) >> 5;        // stages of 32 k
    int xs = d >> 5;             // stages covering the x section (set1 only)
    uint32_t sb = smem_u32(dsm);

    if (tid < 64) sbias[tid] = bias[n0 + tid];
    if (tid < 128) {
        int rr = m0 + tid;
        samp[tid] = (rr < NN) ? g_amp[rr] : 0.f;
        satt[tid] = (rr < NN) ? g_att[rr] : 0.f;
    }

    float c[3][2][4][4];
#pragma unroll
    for (int t = 0; t < 3; t++)
#pragma unroll
        for (int i = 0; i < 2; i++)
#pragma unroll
            for (int j = 0; j < 4; j++)
#pragma unroll
                for (int v = 0; v < 4; v++) c[t][i][j][v] = 0.f;

    auto issue = [&](int s) {
        int bb = s & 1;
        uint32_t base = sb + (uint32_t)(bb * 12800) * 4;
        int kwA = s << 4;
        bool agg = s >= xs;
        // A: 128 rows x 16 words, hi + lo
#pragma unroll
        for (int it = 0; it < 2; it++) {
            int idx = it * 256 + tid;
            int row = idx >> 2, w4 = idx & 3;
            uint32_t soff = (uint32_t)(row * 20 + w4 * 4) * 4;
            int grow = m0 + row;
            bool va = grow < NN;
            size_t oa = va ? ((size_t)grow * KwA + kwA + w4 * 4) : 0;
            cp16(base + soff, fH + oa, va);
            cp16(base + 2560 * 4 + soff, fL + oa, va);
        }
        // B: 3 slabs, 64 rows x 16 words each, hi + lo
        {
            int row = tid >> 2, w4 = tid & 3;
            uint32_t soff = (uint32_t)(row * 20 + w4 * 4) * 4;
            size_t nb = (size_t)(n0 + row) * Kw13;
#pragma unroll
            for (int t = 0; t < 3; t++) {
                bool p = (t == 0) || agg;
                int kwt = (t == 0) ? kwA : ((t == 1) ? (2 * d + kwA) : (4 * d + kwA));
                size_t ob = p ? (nb + kwt + w4 * 4) : 0;
                uint32_t hb = base + (uint32_t)(5120 + t * 2560) * 4;
                cp16(hb + soff, WtHi + ob, p);
                cp16(hb + 1280 * 4 + soff, WtLo + ob, p);
            }
        }
    };

    issue(0);
    CP_COMMIT();

    for (int s = 0; s < S; s++) {
        if (s + 1 < S) { issue(s + 1); CP_COMMIT(); CP_WAIT1(); }
        else CP_WAIT0();
        __syncthreads();
        int bb = s & 1;
        const uint32_t* base = dsm + bb * 12800;
        const uint32_t* AH = base;
        const uint32_t* AL = base + 2560;
        bool agg = s >= xs;
#pragma unroll
        for (int ch = 0; ch < 2; ch++) {
            int kb2 = ch * 8;
            uint32_t ah[2][4], al[2][4];
#pragma unroll
            for (int i = 0; i < 2; i++) {
                int ra = (wm + i * 16 + q) * 20;
                ah[i][0] = AH[ra + kb2 + r];       ah[i][1] = AH[ra + 160 + kb2 + r];
                ah[i][2] = AH[ra + kb2 + r + 4];   ah[i][3] = AH[ra + 160 + kb2 + r + 4];
                al[i][0] = AL[ra + kb2 + r];       al[i][1] = AL[ra + 160 + kb2 + r];
                al[i][2] = AL[ra + kb2 + r + 4];   al[i][3] = AL[ra + 160 + kb2 + r + 4];
            }
#pragma unroll
            for (int t = 0; t < 3; t++) {
                if (t > 0 && !agg) break;
                const uint32_t* BH = base + 5120 + t * 2560;
                const uint32_t* BL = BH + 1280;
#pragma unroll
                for (int j = 0; j < 4; j++) {
                    int rb = (wn + j * 8 + q) * 20;
                    uint32_t bh0 = BH[rb + kb2 + r], bh1 = BH[rb + kb2 + r + 4];
                    uint32_t bl0 = BL[rb + kb2 + r], bl1 = BL[rb + kb2 + r + 4];
#pragma unroll
                    for (int i = 0; i < 2; i++) {
                        MMA_BF16(c[t][i][j], ah[i], bh0, bh1);
                        MMA_BF16(c[t][i][j], ah[i], bl0, bl1);
                        MMA_BF16(c[t][i][j], al[i], bh0, bh1);
                    }
                }
            }
        }
        __syncthreads();
    }

    // ---- epilogue: combine 3 sets + bias + relu + store + BN stats ----
    if (tid < 64) { s_cs[tid] = 0.f; s_cq[tid] = 0.f; }
    __syncthreads();
    float csum[4][2], cssq[4][2];
#pragma unroll
    for (int j = 0; j < 4; j++)
#pragma unroll
        for (int e = 0; e < 2; e++) { csum[j][e] = 0.f; cssq[j][e] = 0.f; }
#pragma unroll
    for (int i = 0; i < 2; i++) {
#pragma unroll
        for (int half = 0; half < 2; half++) {
            int rowl = wm + i * 16 + q + half * 8;
            int row = m0 + rowl;
            bool valid = row < NN;
            float amp = samp[rowl], att = satt[rowl];
#pragma unroll
            for (int j = 0; j < 4; j++) {
#pragma unroll
                for (int e = 0; e < 2; e++) {
                    int lc = wn + j * 8 + 2 * r + e;
                    int vi = half * 2 + e;
                    float v = c[0][i][j][vi] + amp * c[1][i][j][vi]
                            + att * c[2][i][j][vi] + sbias[lc];
                    v = fmaxf(v, 0.f);
                    if (valid) hout[(size_t)row * dout + n0 + lc] = v;
                    else v = 0.f;
                    csum[j][e] += v;
                    cssq[j][e] += v * v;
                }
            }
        }
    }
#pragma unroll
    for (int j = 0; j < 4; j++)
#pragma unroll
        for (int e = 0; e < 2; e++) {
            int lc = wn + j * 8 + 2 * r + e;
            atomicAdd(&s_cs[lc], csum[j][e]);
            atomicAdd(&s_cq[lc], cssq[j][e]);
        }
    __syncthreads();
    if (tid < 64) {
        atomicAdd(&g_colsum[n0 + tid], s_cs[tid]);
        atomicAdd(&g_colssq[n0 + tid], s_cq[tid]);
    }
}

// ---------------- batchnorm stats -> affine coefficients ----------------
__global__ void k_zero_bn() {
    int i = threadIdx.x;
    g_colsum[i] = 0.f; g_colssq[i] = 0.f;
}

__global__ void k_bnfinal(const float* __restrict__ gamma,
                          const float* __restrict__ beta, int dout) {
    int c = threadIdx.x;
    if (c >= dout) return;
    float mean = g_colsum[c] / (float)NN;
    float var  = g_colssq[c] / (float)NN - mean * mean;
    float inv  = rsqrtf(var + 1e-5f);
    g_bnscale[c] = gamma[c] * inv;
    g_bnshift[c] = beta[c] - mean * inv * gamma[c];
}

// ---------------- classifier (applies final BN affine inline) ----------------
__global__ void k_cls(const float* __restrict__ h, const float* __restrict__ Wc,
                      const float* __restrict__ bc, float* __restrict__ out) {
    __shared__ float sW[640];
    __shared__ float sb[16];
    int tid = threadIdx.x;
    for (int i = tid; i < 640; i += 256) sW[i] = Wc[i];
    if (tid < 10) sb[tid] = bc[tid];
    __syncthreads();
    int gwarp = (blockIdx.x * 256 + tid) >> 5;
    int lane = tid & 31;
    if (gwarp >= NN) return;
    float v1 = h[gwarp * 64 + lane] * g_bnscale[lane] + g_bnshift[lane];
    float v2 = h[gwarp * 64 + 32 + lane] * g_bnscale[lane + 32] + g_bnshift[lane + 32];
    float acc[10];
#pragma unroll
    for (int c = 0; c < 10; c++)
        acc[c] = v1 * sW[lane * 10 + c] + v2 * sW[(lane + 32) * 10 + c];
#pragma unroll
    for (int off = 16; off > 0; off >>= 1)
#pragma unroll
        for (int c = 0; c < 10; c++)
            acc[c] += __shfl_down_sync(0xffffffffu, acc[c], off);
    if (lane == 0)
#pragma unroll
        for (int c = 0; c < 10; c++)
            out[gwarp * 10 + c] = acc[c] + sb[c];
}

// ---------------- launch ----------------
extern "C" void kernel_launch(void* const* d_in, const int* in_sizes, int n_in,
                              void* d_out, int out_size) {
    const float* x  = (const float*)d_in[0];
    const int*   ei = (const int*)d_in[1];
    const int* src = ei;
    const int* dst = ei + EE;

    float *hA, *hB;
    uint32_t *WtHi, *WtLo, *fH, *fL;
    cudaGetSymbolAddress((void**)&hA, g_hA);
    cudaGetSymbolAddress((void**)&hB, g_hB);
    cudaGetSymbolAddress((void**)&WtHi, g_WtHi);
    cudaGetSymbolAddress((void**)&WtLo, g_WtLo);
    cudaGetSymbolAddress((void**)&fH, g_featHi);
    cudaGetSymbolAddress((void**)&fL, g_featLo);

    cudaFuncSetAttribute(k_gemm_mma3, cudaFuncAttributeMaxDynamicSharedMemorySize, 102400);

    k_zero_graph<<<(NN + 255) / 256, 256>>>();
    k_degree<<<(EE + 255) / 256, 256>>>(dst);
    k_scan<<<1, 1024>>>();
    k_fill<<<(EE + 255) / 256, 256>>>(src, dst);
    k_ampatt<<<(NN + 255) / 256, 256>>>();

    int dims[5]   = {64, 128, 256, 128, 64};
    int shiftsP[4] = {5, 6, 7, 6};   // log2(d/2)
    const float* xin = x;
    float* bufs[2] = {hA, hB};

    for (int l = 0; l < 4; l++) {
        int d = dims[l], dout = dims[l + 1];
        int K = 13 * d;
        const float* W  = (const float*)d_in[2 + 4 * l];
        const float* b  = (const float*)d_in[3 + 4 * l];
        const float* gm = (const float*)d_in[4 + 4 * l];
        const float* bt = (const float*)d_in[5 + 4 * l];
        float* hout = bufs[l & 1];

        k_feat5<<<((NN << shiftsP[l]) + 255) / 256, 256>>>(xin, d, shiftsP[l], l > 0, fH, fL);
        dim3 tg(K / 32, dout / 32);
        k_transpose<<<tg, dim3(32, 8)>>>(W, WtHi, WtLo, K, dout);
        k_zero_bn<<<1, 256>>>();

        dim3 grid((NN + 127) / 128, dout / 64);
        k_gemm_mma3<<<grid, 256, 102400>>>(fH, fL, WtHi, WtLo, b, hout, d, dout);

        k_bnfinal<<<1, 256>>>(gm, bt, dout);
        xin = hout;
    }

    k_cls<<<NN / 8, 256>>>(xin, (const float*)d_in[18], (const float*)d_in[19],
                           (float*)d_out);
}